// round 14
// baseline (speedup 1.0000x reference)
#include <cuda_runtime.h>
#include <cuda_bf16.h>
#include <math.h>

// Problem shape (fixed by the dataset)
#define B_DIM   8192
#define IN_DIM  4096
#define OUT_DIM 4096

// Exact expquantize: clamp to [-1,1], snap |x| to nearest 2^k (round-half-even),
// zero anything below 2^-2. Used for bias and the (never-taken here) fallback.
__device__ __forceinline__ float expquant(float x) {
    float c = fminf(fmaxf(x, -1.0f), 1.0f);
    float a = fabsf(c);
    // log2f(0) = -inf -> rintf(-inf) = -inf -> exp2f(-inf) = 0
    float y = exp2f(rintf(log2f(a)));
    y = copysignf(y, x);
    return (fabsf(y) < 0.25f) ? 0.0f : y;
}

// Conservative survival threshold: expquant(x) != 0 ==> |x| >= 2^-2.5 ~= 0.17678.
// Flag at 0.17 (slightly below): any value that could survive definitely flags
// its row; flagged rows go through the exact dense fallback.
#define SURVIVE_THRESH 0.17f

#define COLS    16          // output columns per block
#define THREADS 256         // 8 warps
#define NBLOCKS (OUT_DIM / COLS)   // 256

// Fused kernel: each block owns a 16-column stripe of the output.
// Phase 1: scan its 16 weight rows (any-survivor flag) + quantize 16 bias vals.
// Phase 2: stream all B_DIM rows of the stripe (bias fast path / dense fallback).
__global__ void __launch_bounds__(THREADS) fused_qlinear_kernel(
    const float* __restrict__ x,        // [B_DIM, IN_DIM]
    const float* __restrict__ weight,   // [OUT_DIM, IN_DIM]
    const float* __restrict__ bias,     // [OUT_DIM]
    float* __restrict__ out             // [B_DIM, OUT_DIM]
) {
    __shared__ int   sflag[COLS];
    __shared__ float sbq[COLS];

    const int o0   = blockIdx.x * COLS;
    const int tid  = threadIdx.x;
    const int wid  = tid >> 5;
    const int lane = tid & 31;

    // ---- Phase 1: scan (warp w handles weight rows o0+2w, o0+2w+1) ----
    #pragma unroll
    for (int rr = 0; rr < 2; rr++) {
        const int row = o0 + wid * 2 + rr;
        const float4* wr = reinterpret_cast<const float4*>(weight + (size_t)row * IN_DIM);
        int any = 0;
        #pragma unroll 8
        for (int i = 0; i < (IN_DIM / 4) / 32; i++) {   // 32 iterations
            float4 v = __ldcs(wr + i * 32 + lane);      // streaming, no L2 reuse
            any |= (fabsf(v.x) >= SURVIVE_THRESH);
            any |= (fabsf(v.y) >= SURVIVE_THRESH);
            any |= (fabsf(v.z) >= SURVIVE_THRESH);
            any |= (fabsf(v.w) >= SURVIVE_THRESH);
        }
        any = __any_sync(0xffffffffu, any);
        if (lane == 0) sflag[wid * 2 + rr] = any;
    }
    if (tid < COLS) sbq[tid] = expquant(bias[o0 + tid]);
    __syncthreads();

    // Combined flag for the whole stripe (4x int4 broadcast loads from smem)
    const int4* sfv = reinterpret_cast<const int4*>(sflag);
    int4 fA = sfv[0], fB = sfv[1], fC = sfv[2], fD = sfv[3];
    int anyall = fA.x | fA.y | fA.z | fA.w | fB.x | fB.y | fB.z | fB.w
               | fC.x | fC.y | fC.z | fC.w | fD.x | fD.y | fD.z | fD.w;

    // Emit mapping: team of 4 threads per output row, each thread a float4
    const int sub  = tid & 3;           // which 4-col chunk of the stripe
    const int team = tid >> 2;          // 0..63: starting row
    const float4 bq = reinterpret_cast<const float4*>(sbq)[sub];
    float* p = out + (size_t)team * OUT_DIM + o0 + sub * 4;

    if (anyall == 0) {
        // ---- Fast path: pure streaming stores of the quantized bias ----
        #pragma unroll 8
        for (int i = 0; i < B_DIM / 64; i++) {          // 128 iterations
            __stcs(reinterpret_cast<float4*>(p), bq);
            p += (size_t)64 * OUT_DIM;
        }
        return;
    }

    // ---- Fallback: exact dense dot for flagged columns (never taken here) ----
    int4 f = sfv[sub];
    int fl[4] = {f.x, f.y, f.z, f.w};
    for (int i = 0; i < B_DIM / 64; i++) {
        const int b = team + i * 64;
        const float* xr = x + (size_t)b * IN_DIM;
        float acc[4] = {bq.x, bq.y, bq.z, bq.w};
        #pragma unroll
        for (int j = 0; j < 4; j++) {
            if (fl[j]) {
                const float* wr = weight + (size_t)(o0 + sub * 4 + j) * IN_DIM;
                float s = 0.0f;
                for (int k = 0; k < IN_DIM; k++) s += xr[k] * expquant(wr[k]);
                acc[j] += s;
            }
        }
        float4 rv = {acc[0], acc[1], acc[2], acc[3]};
        *reinterpret_cast<float4*>(p) = rv;
        p += (size_t)64 * OUT_DIM;
    }
}

extern "C" void kernel_launch(void* const* d_in, const int* in_sizes, int n_in,
                              void* d_out, int out_size) {
    const float* x      = (const float*)d_in[0];   // [8192, 4096]
    const float* weight = (const float*)d_in[1];   // [4096, 4096]
    const float* bias   = (const float*)d_in[2];   // [4096]
    float* out          = (float*)d_out;           // [8192, 4096]

    (void)in_sizes; (void)n_in; (void)out_size;

    fused_qlinear_kernel<<<NBLOCKS, THREADS>>>(x, weight, bias, out);
}